// round 3
// baseline (speedup 1.0000x reference)
#include <cuda_runtime.h>

#define NN   16384
#define EE   524288
#define GG   64
#define HID  128
#define NG   51
#define NL   6

// ---------------- scratch (device globals; no allocation allowed) ----------
__device__ float g_h   [(size_t)NN * HID];   // node features
__device__ float g_h2  [(size_t)NN * HID];   // final MLP output
__device__ float g_xh  [(size_t)NN * HID];   // h @ cl1_w
__device__ float g_agg [(size_t)NN * HID];   // segment-sum accumulator
__device__ float g_attrT[(size_t)NG * EE];   // gaussian smearing, [k][e] layout
__device__ float g_C   [EE];                 // cosine cutoff
__device__ float g_cnt [GG];                 // per-graph node counts

// ---------------- helpers --------------------------------------------------
__device__ __forceinline__ float ssp_f(float x) {
    // shifted softplus: log(1+exp(x)) - log(2)
    float sp = (x > 15.f) ? x : __logf(1.f + __expf(x));
    return sp - 0.69314718055994531f;
}

__device__ __forceinline__ void red_add_v4(float* addr, float4 v) {
    asm volatile("red.global.add.v4.f32 [%0], {%1,%2,%3,%4};"
                 :: "l"(addr), "f"(v.x), "f"(v.y), "f"(v.z), "f"(v.w)
                 : "memory");
}

// ---- packed f32x2 primitives (FFMA2: ptxas only emits via fma.rn.f32x2) ----
__device__ __forceinline__ unsigned long long dup2(float a) {
    unsigned long long r;
    asm("mov.b64 %0, {%1, %1};" : "=l"(r) : "f"(a));
    return r;
}
__device__ __forceinline__ void ffma2(unsigned long long& acc,
                                      unsigned long long a, unsigned long long b) {
    asm("fma.rn.f32x2 %0, %1, %2, %0;" : "+l"(acc) : "l"(a), "l"(b));
}
__device__ __forceinline__ unsigned long long mul2(unsigned long long a,
                                                   unsigned long long b) {
    unsigned long long r;
    asm("mul.rn.f32x2 %0, %1, %2;" : "=l"(r) : "l"(a), "l"(b));
    return r;
}
__device__ __forceinline__ float2 unpack2(unsigned long long v) {
    float2 r;
    asm("mov.b64 {%0, %1}, %2;" : "=f"(r.x), "=f"(r.y) : "l"(v));
    return r;
}

// shared inner block: acc2[8][4] += A-col (8 floats) x B-row pair (8 floats)
#define FFMA2_BLOCK(acc2, av, bq0, bq1)                                   \
    _Pragma("unroll")                                                     \
    for (int _i = 0; _i < 8; _i++) {                                      \
        unsigned long long _ad = dup2((av)[_i]);                          \
        ffma2((acc2)[_i][0], _ad, (bq0).x);                               \
        ffma2((acc2)[_i][1], _ad, (bq0).y);                               \
        ffma2((acc2)[_i][2], _ad, (bq1).x);                               \
        ffma2((acc2)[_i][3], _ad, (bq1).y);                               \
    }

// ---------------- setup kernels --------------------------------------------
// h[n] = emb_table[z[n]]
__global__ void k_init_h(const int* __restrict__ z, const float* __restrict__ emb) {
    int idx = blockIdx.x * 256 + threadIdx.x;      // NN*32 threads
    int n = idx >> 5, q = idx & 31;
    ((float4*)g_h)[idx] = ((const float4*)(emb + (size_t)z[n] * HID))[q];
}

// per-edge: distance, cosine cutoff, 51 gaussians (stored transposed [k][e])
__global__ void k_edge_pre(const float* __restrict__ pos, const int* __restrict__ ei) {
    __shared__ float sA[NG * 128];
    int t = threadIdx.x;
    int eBase = blockIdx.x * 128;
    int e = eBase + t;
    int r = ei[e], c = ei[EE + e];
    float dx = pos[r*3+0] - pos[c*3+0];
    float dy = pos[r*3+1] - pos[c*3+1];
    float dz = pos[r*3+2] - pos[c*3+2];
    float d = sqrtf(dx*dx + dy*dy + dz*dz);
    g_C[e] = 0.5f * (__cosf(d * 0.31415926535897931f) + 1.f);
#pragma unroll
    for (int k = 0; k < NG; k++) {
        float u = d - 0.2f * (float)k;
        sA[k * 128 + t] = __expf(-12.5f * u * u);
    }
    __syncthreads();
    for (int i = t; i < NG * 128; i += 128) {
        int k = i >> 7, q = i & 127;
        g_attrT[(size_t)k * EE + eBase + q] = sA[i];
    }
}

__global__ void k_zero_agg() {
    int idx = blockIdx.x * 256 + threadIdx.x;      // NN*HID/4 threads
    ((float4*)g_agg)[idx] = make_float4(0.f, 0.f, 0.f, 0.f);
}

// ---------------- node GEMM: xh = h @ W (128x128, no bias, f32x2) ----------
__global__ __launch_bounds__(256, 1)
void k_gemm_xh(const float* __restrict__ W) {
    extern __shared__ float sm[];
    float* sX = sm;                  // 128*132
    float* sW = sm + 128 * 132;      // 128*128
    int tid = threadIdx.x;
    int rBase = blockIdx.x * 128;

    for (int i = tid; i < 128 * 32; i += 256) {
        int r = i >> 5, c = i & 31;
        ((float4*)(sX + r * 132))[c] =
            ((const float4*)(g_h + (size_t)(rBase + r) * HID))[c];
    }
    for (int i = tid; i < 128 * 32; i += 256)
        ((float4*)sW)[i] = ((const float4*)W)[i];
    __syncthreads();

    int tr = tid >> 4, tc = tid & 15, r0 = tr * 8, f0 = tc * 8;
    unsigned long long acc2[8][4];
#pragma unroll
    for (int i = 0; i < 8; i++)
#pragma unroll
        for (int j = 0; j < 4; j++) acc2[i][j] = 0ull;

#pragma unroll 1
    for (int k4 = 0; k4 < 128; k4 += 4) {
        float4 av4[8];
#pragma unroll
        for (int i = 0; i < 8; i++)
            av4[i] = *(const float4*)&sX[(r0 + i) * 132 + k4];
#pragma unroll
        for (int kk = 0; kk < 4; kk++) {
            ulonglong2 bq0 = *(const ulonglong2*)&sW[(k4 + kk) * 128 + f0];
            ulonglong2 bq1 = *(const ulonglong2*)&sW[(k4 + kk) * 128 + f0 + 4];
            float av[8];
#pragma unroll
            for (int i = 0; i < 8; i++) av[i] = ((const float*)&av4[i])[kk];
            FFMA2_BLOCK(acc2, av, bq0, bq1);
        }
    }
#pragma unroll
    for (int i = 0; i < 8; i++) {
        float2 u0 = unpack2(acc2[i][0]), u1 = unpack2(acc2[i][1]);
        float2 u2 = unpack2(acc2[i][2]), u3 = unpack2(acc2[i][3]);
        float* dst = g_xh + (size_t)(rBase + r0 + i) * HID + f0;
        *(float4*)dst       = make_float4(u0.x, u0.y, u1.x, u1.y);
        *(float4*)(dst + 4) = make_float4(u2.x, u2.y, u3.x, u3.y);
    }
}

// ---------------- fused edge kernel (f32x2 packed math) ---------------------
// per 128-edge tile:
//   T  = ssp(edge_attr @ W1 + b1)            (K=51)
//   Wf = (T @ W2 + b2) * C                   (K=128)
//   red.add( agg[row], Wf * xh[col] )
__global__ __launch_bounds__(256, 1)
void k_edge(const int* __restrict__ ei,
            const float* __restrict__ W1, const float* __restrict__ B1,
            const float* __restrict__ W2, const float* __restrict__ B2) {
    extern __shared__ float sm[];
    float* sAT = sm;                       // NG*128
    float* sW1 = sAT + NG * 128;           // NG*128
    float* sW2 = sW1 + NG * 128;           // 128*128
    float* sT  = sW2 + 128 * 128;          // 128*132
    float* sC  = sT  + 128 * 132;          // 128
    int*   sRow = (int*)(sC + 128);        // 128
    int*   sCol = sRow + 128;              // 128

    int tid = threadIdx.x;
    int eBase = blockIdx.x * 128;

    for (int i = tid; i < NG * 32; i += 256) {
        int k = i >> 5, q = i & 31;
        ((float4*)sAT)[i] = ((const float4*)(g_attrT + (size_t)k * EE + eBase))[q];
    }
    for (int i = tid; i < NG * 32; i += 256)
        ((float4*)sW1)[i] = ((const float4*)W1)[i];
    for (int i = tid; i < 128 * 32; i += 256)
        ((float4*)sW2)[i] = ((const float4*)W2)[i];
    if (tid < 128) {
        sC[tid]   = g_C[eBase + tid];
        sRow[tid] = ei[eBase + tid];
        sCol[tid] = ei[EE + eBase + tid];
    }
    __syncthreads();

    int tr = tid >> 4, tc = tid & 15, e0 = tr * 8, f0 = tc * 8;
    unsigned long long acc2[8][4];

    // ---- GEMM1: K = 51, bias init ----
    {
        ulonglong2 bb0 = *(const ulonglong2*)(B1 + f0);
        ulonglong2 bb1 = *(const ulonglong2*)(B1 + f0 + 4);
#pragma unroll
        for (int i = 0; i < 8; i++) {
            acc2[i][0] = bb0.x; acc2[i][1] = bb0.y;
            acc2[i][2] = bb1.x; acc2[i][3] = bb1.y;
        }
    }
#pragma unroll 3
    for (int k = 0; k < NG; k++) {
        float4 a0 = *(const float4*)&sAT[k * 128 + e0];
        float4 a1 = *(const float4*)&sAT[k * 128 + e0 + 4];
        ulonglong2 bq0 = *(const ulonglong2*)&sW1[k * 128 + f0];
        ulonglong2 bq1 = *(const ulonglong2*)&sW1[k * 128 + f0 + 4];
        float av[8] = {a0.x,a0.y,a0.z,a0.w,a1.x,a1.y,a1.z,a1.w};
        FFMA2_BLOCK(acc2, av, bq0, bq1);
    }

    // ssp -> sT (distinct buffer; sync before GEMM2 reads)
#pragma unroll
    for (int i = 0; i < 8; i++)
#pragma unroll
        for (int j2 = 0; j2 < 4; j2++) {
            float2 v = unpack2(acc2[i][j2]);
            sT[(e0 + i) * 132 + f0 + 2*j2]     = ssp_f(v.x);
            sT[(e0 + i) * 132 + f0 + 2*j2 + 1] = ssp_f(v.y);
        }
    __syncthreads();

    // ---- GEMM2: K = 128, bias init ----
    {
        ulonglong2 bb0 = *(const ulonglong2*)(B2 + f0);
        ulonglong2 bb1 = *(const ulonglong2*)(B2 + f0 + 4);
#pragma unroll
        for (int i = 0; i < 8; i++) {
            acc2[i][0] = bb0.x; acc2[i][1] = bb0.y;
            acc2[i][2] = bb1.x; acc2[i][3] = bb1.y;
        }
    }
#pragma unroll 1
    for (int k4 = 0; k4 < 128; k4 += 4) {
        float4 av4[8];
#pragma unroll
        for (int i = 0; i < 8; i++)
            av4[i] = *(const float4*)&sT[(e0 + i) * 132 + k4];
#pragma unroll
        for (int kk = 0; kk < 4; kk++) {
            ulonglong2 bq0 = *(const ulonglong2*)&sW2[(k4 + kk) * 128 + f0];
            ulonglong2 bq1 = *(const ulonglong2*)&sW2[(k4 + kk) * 128 + f0 + 4];
            float av[8];
#pragma unroll
            for (int i = 0; i < 8; i++) av[i] = ((const float*)&av4[i])[kk];
            FFMA2_BLOCK(acc2, av, bq0, bq1);
        }
    }

    // epilogue: *C, gather xh[col], scatter-add to agg[row] (stays packed)
#pragma unroll
    for (int i = 0; i < 8; i++) {
        int le = e0 + i;
        unsigned long long cd = dup2(sC[le]);
        int cl = sCol[le], rw = sRow[le];
        const float* xr = g_xh + (size_t)cl * HID + f0;
        ulonglong2 xq0 = *(const ulonglong2*)xr;
        ulonglong2 xq1 = *(const ulonglong2*)(xr + 4);
        unsigned long long p0 = mul2(mul2(acc2[i][0], cd), xq0.x);
        unsigned long long p1 = mul2(mul2(acc2[i][1], cd), xq0.y);
        unsigned long long p2 = mul2(mul2(acc2[i][2], cd), xq1.x);
        unsigned long long p3 = mul2(mul2(acc2[i][3], cd), xq1.y);
        float2 u0 = unpack2(p0), u1 = unpack2(p1);
        float2 u2 = unpack2(p2), u3 = unpack2(p3);
        float* ap = g_agg + (size_t)rw * HID + f0;
        red_add_v4(ap,     make_float4(u0.x, u0.y, u1.x, u1.y));
        red_add_v4(ap + 4, make_float4(u2.x, u2.y, u3.x, u3.y));
    }
}

// ---------------- fused dual node GEMM (f32x2) ------------------------------
// Y = ssp(X @ W1 + b1) @ W2 + b2 ; addMode: dst += Y, else dst = Y
__global__ __launch_bounds__(256, 1)
void k_dual(const float* __restrict__ X,
            const float* __restrict__ W1, const float* __restrict__ B1,
            const float* __restrict__ W2, const float* __restrict__ B2,
            float* __restrict__ dst, int addMode) {
    extern __shared__ float sm[];
    float* sX  = sm;                  // 128*132 (re-used as T after GEMM1)
    float* sW1 = sm + 128 * 132;      // 128*128
    float* sW2 = sW1 + 128 * 128;     // 128*128
    int tid = threadIdx.x;
    int rBase = blockIdx.x * 128;

    for (int i = tid; i < 128 * 32; i += 256) {
        int r = i >> 5, c = i & 31;
        ((float4*)(sX + r * 132))[c] =
            ((const float4*)(X + (size_t)(rBase + r) * HID))[c];
    }
    for (int i = tid; i < 128 * 32; i += 256)
        ((float4*)sW1)[i] = ((const float4*)W1)[i];
    for (int i = tid; i < 128 * 32; i += 256)
        ((float4*)sW2)[i] = ((const float4*)W2)[i];
    __syncthreads();

    int tr = tid >> 4, tc = tid & 15, r0 = tr * 8, f0 = tc * 8;
    unsigned long long acc2[8][4];

    // ---- GEMM1 ----
    {
        ulonglong2 bb0 = *(const ulonglong2*)(B1 + f0);
        ulonglong2 bb1 = *(const ulonglong2*)(B1 + f0 + 4);
#pragma unroll
        for (int i = 0; i < 8; i++) {
            acc2[i][0] = bb0.x; acc2[i][1] = bb0.y;
            acc2[i][2] = bb1.x; acc2[i][3] = bb1.y;
        }
    }
#pragma unroll 1
    for (int k4 = 0; k4 < 128; k4 += 4) {
        float4 av4[8];
#pragma unroll
        for (int i = 0; i < 8; i++)
            av4[i] = *(const float4*)&sX[(r0 + i) * 132 + k4];
#pragma unroll
        for (int kk = 0; kk < 4; kk++) {
            ulonglong2 bq0 = *(const ulonglong2*)&sW1[(k4 + kk) * 128 + f0];
            ulonglong2 bq1 = *(const ulonglong2*)&sW1[(k4 + kk) * 128 + f0 + 4];
            float av[8];
#pragma unroll
            for (int i = 0; i < 8; i++) av[i] = ((const float*)&av4[i])[kk];
            FFMA2_BLOCK(acc2, av, bq0, bq1);
        }
    }
    __syncthreads();   // everyone done reading sX before it becomes T
#pragma unroll
    for (int i = 0; i < 8; i++)
#pragma unroll
        for (int j2 = 0; j2 < 4; j2++) {
            float2 v = unpack2(acc2[i][j2]);
            sX[(r0 + i) * 132 + f0 + 2*j2]     = ssp_f(v.x);
            sX[(r0 + i) * 132 + f0 + 2*j2 + 1] = ssp_f(v.y);
        }
    __syncthreads();

    // ---- GEMM2 ----
    {
        ulonglong2 bb0 = *(const ulonglong2*)(B2 + f0);
        ulonglong2 bb1 = *(const ulonglong2*)(B2 + f0 + 4);
#pragma unroll
        for (int i = 0; i < 8; i++) {
            acc2[i][0] = bb0.x; acc2[i][1] = bb0.y;
            acc2[i][2] = bb1.x; acc2[i][3] = bb1.y;
        }
    }
#pragma unroll 1
    for (int k4 = 0; k4 < 128; k4 += 4) {
        float4 av4[8];
#pragma unroll
        for (int i = 0; i < 8; i++)
            av4[i] = *(const float4*)&sX[(r0 + i) * 132 + k4];
#pragma unroll
        for (int kk = 0; kk < 4; kk++) {
            ulonglong2 bq0 = *(const ulonglong2*)&sW2[(k4 + kk) * 128 + f0];
            ulonglong2 bq1 = *(const ulonglong2*)&sW2[(k4 + kk) * 128 + f0 + 4];
            float av[8];
#pragma unroll
            for (int i = 0; i < 8; i++) av[i] = ((const float*)&av4[i])[kk];
            FFMA2_BLOCK(acc2, av, bq0, bq1);
        }
    }
#pragma unroll
    for (int i = 0; i < 8; i++) {
        float2 u0 = unpack2(acc2[i][0]), u1 = unpack2(acc2[i][1]);
        float2 u2 = unpack2(acc2[i][2]), u3 = unpack2(acc2[i][3]);
        float* dp = dst + (size_t)(rBase + r0 + i) * HID + f0;
        if (addMode) {
            float4 d0 = *(float4*)dp, d1 = *(float4*)(dp + 4);
            d0.x += u0.x; d0.y += u0.y; d0.z += u1.x; d0.w += u1.y;
            d1.x += u2.x; d1.y += u2.y; d1.z += u3.x; d1.w += u3.y;
            *(float4*)dp = d0; *(float4*)(dp + 4) = d1;
        } else {
            *(float4*)dp       = make_float4(u0.x, u0.y, u1.x, u1.y);
            *(float4*)(dp + 4) = make_float4(u2.x, u2.y, u3.x, u3.y);
        }
    }
}

// ---------------- pooling --------------------------------------------------
__global__ void k_zero_out(float* __restrict__ out) {
    int idx = blockIdx.x * 256 + threadIdx.x;
    if (idx < GG * HID) out[idx] = 0.f;
    if (idx < GG) g_cnt[idx] = 0.f;
}

__global__ void k_pool(const int* __restrict__ batch, float* __restrict__ out) {
    int idx = blockIdx.x * 256 + threadIdx.x;      // NN*32 threads
    int n = idx >> 5, q = idx & 31;
    float4 v = ((const float4*)(g_h2 + (size_t)n * HID))[q];
    int b = batch[n];
    red_add_v4(out + (size_t)b * HID + q * 4, v);
    if (q == 0) atomicAdd(&g_cnt[b], 1.f);
}

__global__ void k_div(float* __restrict__ out) {
    int idx = blockIdx.x * 256 + threadIdx.x;
    if (idx < GG * HID) {
        int g = idx >> 7;
        out[idx] = out[idx] / fmaxf(g_cnt[g], 1.f);
    }
}

// ---------------- host side ------------------------------------------------
extern "C" void kernel_launch(void* const* d_in, const int* in_sizes, int n_in,
                              void* d_out, int out_size) {
    const int*   z       = (const int*)  d_in[0];
    const float* pos     = (const float*)d_in[1];
    const int*   batch   = (const int*)  d_in[2];
    const int*   ei      = (const int*)  d_in[3];
    const float* emb     = (const float*)d_in[4];
    const float* mlp1_w  = (const float*)d_in[5];
    const float* mlp1_b  = (const float*)d_in[6];
    const float* mlp2_w  = (const float*)d_in[7];
    const float* mlp2_b  = (const float*)d_in[8];
    const float* cl1_w   = (const float*)d_in[9];
    const float* cl2_w   = (const float*)d_in[10];
    const float* cl2_b   = (const float*)d_in[11];
    const float* lin_w   = (const float*)d_in[12];
    const float* lin_b   = (const float*)d_in[13];
    const float* out1_w  = (const float*)d_in[14];
    const float* out1_b  = (const float*)d_in[15];
    const float* out2_w  = (const float*)d_in[16];
    const float* out2_b  = (const float*)d_in[17];
    float* out = (float*)d_out;

    float *p_agg, *p_h, *p_h2;
    cudaGetSymbolAddress((void**)&p_agg, g_agg);
    cudaGetSymbolAddress((void**)&p_h,   g_h);
    cudaGetSymbolAddress((void**)&p_h2,  g_h2);

    const int smEdge = (NG*128*2 + 128*128 + 128*132 + 128) * 4 + 256 * 4;
    const int smDual = (128*132 + 2*128*128) * 4;
    const int smG    = (128*132 + 128*128) * 4;
    cudaFuncSetAttribute(k_edge,    cudaFuncAttributeMaxDynamicSharedMemorySize, smEdge);
    cudaFuncSetAttribute(k_dual,    cudaFuncAttributeMaxDynamicSharedMemorySize, smDual);
    cudaFuncSetAttribute(k_gemm_xh, cudaFuncAttributeMaxDynamicSharedMemorySize, smG);

    k_init_h  <<<NN * 32 / 256, 256>>>(z, emb);
    k_edge_pre<<<EE / 128, 128>>>(pos, ei);

    for (int l = 0; l < NL; l++) {
        k_zero_agg<<<NN * HID / 4 / 256, 256>>>();
        k_gemm_xh<<<NN / 128, 256, smG>>>(cl1_w + (size_t)l * HID * HID);
        k_edge<<<EE / 128, 256, smEdge>>>(ei,
            mlp1_w + (size_t)l * NG * HID, mlp1_b + (size_t)l * HID,
            mlp2_w + (size_t)l * HID * HID, mlp2_b + (size_t)l * HID);
        k_dual<<<NN / 128, 256, smDual>>>(p_agg,
            cl2_w + (size_t)l * HID * HID, cl2_b + (size_t)l * HID,
            lin_w + (size_t)l * HID * HID, lin_b + (size_t)l * HID,
            p_h, 1);
    }

    // final output MLP then scatter-mean pooling
    k_dual<<<NN / 128, 256, smDual>>>(p_h, out1_w, out1_b, out2_w, out2_b, p_h2, 0);
    k_zero_out<<<(GG * HID + 255) / 256, 256>>>(out);
    k_pool<<<NN * 32 / 256, 256>>>(batch, out);
    k_div<<<(GG * HID + 255) / 256, 256>>>(out);
}

// round 5
// speedup vs baseline: 1.2641x; 1.2641x over previous
#include <cuda_runtime.h>

#define NN   16384
#define EE   524288
#define GG   64
#define HID  128
#define NG   51
#define NL   6

// ---------------- scratch (device globals; no allocation allowed) ----------
__device__ float g_h   [(size_t)NN * HID];   // node features
__device__ float g_h2  [(size_t)NN * HID];   // final MLP output
__device__ float g_xh  [(size_t)NN * HID];   // h @ cl1_w
__device__ float g_agg [(size_t)NN * HID];   // segment-sum accumulator
__device__ float g_attrT[(size_t)NG * EE];   // gaussian smearing, [k][e] layout
__device__ float g_C   [EE];                 // cosine cutoff
__device__ float g_cnt [GG];                 // per-graph node counts

// ---------------- helpers --------------------------------------------------
__device__ __forceinline__ float ssp_f(float x) {
    float sp = (x > 15.f) ? x : __logf(1.f + __expf(x));
    return sp - 0.69314718055994531f;
}

__device__ __forceinline__ void red_add_v4(float* addr, float4 v) {
    asm volatile("red.global.add.v4.f32 [%0], {%1,%2,%3,%4};"
                 :: "l"(addr), "f"(v.x), "f"(v.y), "f"(v.z), "f"(v.w)
                 : "memory");
}

// ---- packed f32x2 primitives (FFMA2: ptxas only emits via fma.rn.f32x2) ----
__device__ __forceinline__ unsigned long long dup2(float a) {
    unsigned long long r;
    asm("mov.b64 %0, {%1, %1};" : "=l"(r) : "f"(a));
    return r;
}
__device__ __forceinline__ void ffma2(unsigned long long& acc,
                                      unsigned long long a, unsigned long long b) {
    asm("fma.rn.f32x2 %0, %1, %2, %0;" : "+l"(acc) : "l"(a), "l"(b));
}
__device__ __forceinline__ unsigned long long mul2(unsigned long long a,
                                                   unsigned long long b) {
    unsigned long long r;
    asm("mul.rn.f32x2 %0, %1, %2;" : "=l"(r) : "l"(a), "l"(b));
    return r;
}
__device__ __forceinline__ float2 unpack2(unsigned long long v) {
    float2 r;
    asm("mov.b64 {%0, %1}, %2;" : "=f"(r.x), "=f"(r.y) : "l"(v));
    return r;
}

// inner block for 8x4 thread tile: acc2[8][2] += av[8] (x) B pair-of-pairs
#define FFMA2_BLOCK84(acc2, av, bq)                                       \
    _Pragma("unroll")                                                     \
    for (int _i = 0; _i < 8; _i++) {                                      \
        unsigned long long _ad = dup2((av)[_i]);                          \
        ffma2((acc2)[_i][0], _ad, (bq).x);                                \
        ffma2((acc2)[_i][1], _ad, (bq).y);                                \
    }

// ---------------- setup kernels --------------------------------------------
__global__ void k_init_h(const int* __restrict__ z, const float* __restrict__ emb) {
    int idx = blockIdx.x * 256 + threadIdx.x;      // NN*32 threads
    int n = idx >> 5, q = idx & 31;
    ((float4*)g_h)[idx] = ((const float4*)(emb + (size_t)z[n] * HID))[q];
}

__global__ void k_edge_pre(const float* __restrict__ pos, const int* __restrict__ ei) {
    __shared__ float sA[NG * 128];
    int t = threadIdx.x;
    int eBase = blockIdx.x * 128;
    int e = eBase + t;
    int r = ei[e], c = ei[EE + e];
    float dx = pos[r*3+0] - pos[c*3+0];
    float dy = pos[r*3+1] - pos[c*3+1];
    float dz = pos[r*3+2] - pos[c*3+2];
    float d = sqrtf(dx*dx + dy*dy + dz*dz);
    g_C[e] = 0.5f * (__cosf(d * 0.31415926535897931f) + 1.f);
#pragma unroll
    for (int k = 0; k < NG; k++) {
        float u = d - 0.2f * (float)k;
        sA[k * 128 + t] = __expf(-12.5f * u * u);
    }
    __syncthreads();
    for (int i = t; i < NG * 128; i += 128) {
        int k = i >> 7, q = i & 127;
        g_attrT[(size_t)k * EE + eBase + q] = sA[i];
    }
}

__global__ void k_zero_agg() {
    int idx = blockIdx.x * 256 + threadIdx.x;      // NN*HID/4 threads
    ((float4*)g_agg)[idx] = make_float4(0.f, 0.f, 0.f, 0.f);
}

// ---------------- node GEMM: xh = h @ W (512 thr, 8x4 tile) ----------------
__global__ __launch_bounds__(512, 1)
void k_gemm_xh(const float* __restrict__ W) {
    extern __shared__ float sm[];
    float* sX = sm;                  // 128*132
    float* sW = sm + 128 * 132;      // 128*128
    int tid = threadIdx.x;
    int rBase = blockIdx.x * 128;

    for (int i = tid; i < 128 * 32; i += 512) {
        int r = i >> 5, c = i & 31;
        ((float4*)(sX + r * 132))[c] =
            ((const float4*)(g_h + (size_t)(rBase + r) * HID))[c];
    }
    for (int i = tid; i < 128 * 32; i += 512)
        ((float4*)sW)[i] = ((const float4*)W)[i];
    __syncthreads();

    int tr = tid >> 5, tc = tid & 31, r0 = tr * 8, f0 = tc * 4;
    unsigned long long acc2[8][2];
#pragma unroll
    for (int i = 0; i < 8; i++) { acc2[i][0] = 0ull; acc2[i][1] = 0ull; }

#pragma unroll 1
    for (int k4 = 0; k4 < 128; k4 += 4) {
        float4 av4[8];
#pragma unroll
        for (int i = 0; i < 8; i++)
            av4[i] = *(const float4*)&sX[(r0 + i) * 132 + k4];
#pragma unroll
        for (int kk = 0; kk < 4; kk++) {
            ulonglong2 bq = *(const ulonglong2*)&sW[(k4 + kk) * 128 + f0];
            float av[8];
#pragma unroll
            for (int i = 0; i < 8; i++) av[i] = ((const float*)&av4[i])[kk];
            FFMA2_BLOCK84(acc2, av, bq);
        }
    }
#pragma unroll
    for (int i = 0; i < 8; i++) {
        float2 u0 = unpack2(acc2[i][0]), u1 = unpack2(acc2[i][1]);
        *(float4*)(g_xh + (size_t)(rBase + r0 + i) * HID + f0) =
            make_float4(u0.x, u0.y, u1.x, u1.y);
    }
}

// ---------------- fused edge kernel (512 thr, 8x4 tile) ---------------------
__global__ __launch_bounds__(512, 1)
void k_edge(const int* __restrict__ ei,
            const float* __restrict__ W1, const float* __restrict__ B1,
            const float* __restrict__ W2, const float* __restrict__ B2) {
    extern __shared__ float sm[];
    float* sAT = sm;                       // NG*128
    float* sW1 = sAT + NG * 128;           // NG*128
    float* sW2 = sW1 + NG * 128;           // 128*128
    float* sT  = sW2 + 128 * 128;          // 128*132
    float* sC  = sT  + 128 * 132;          // 128
    int*   sRow = (int*)(sC + 128);        // 128
    int*   sCol = sRow + 128;              // 128

    int tid = threadIdx.x;
    int eBase = blockIdx.x * 128;

    for (int i = tid; i < NG * 32; i += 512) {
        int k = i >> 5, q = i & 31;
        ((float4*)sAT)[i] = ((const float4*)(g_attrT + (size_t)k * EE + eBase))[q];
    }
    for (int i = tid; i < NG * 32; i += 512)
        ((float4*)sW1)[i] = ((const float4*)W1)[i];
    for (int i = tid; i < 128 * 32; i += 512)
        ((float4*)sW2)[i] = ((const float4*)W2)[i];
    if (tid < 128) {
        sC[tid]   = g_C[eBase + tid];
        sRow[tid] = ei[eBase + tid];
        sCol[tid] = ei[EE + eBase + tid];
    }
    __syncthreads();

    int tr = tid >> 5, tc = tid & 31, e0 = tr * 8, f0 = tc * 4;
    unsigned long long acc2[8][2];

    // ---- GEMM1: K = 51 ----
    {
        ulonglong2 bb = *(const ulonglong2*)(B1 + f0);
#pragma unroll
        for (int i = 0; i < 8; i++) { acc2[i][0] = bb.x; acc2[i][1] = bb.y; }
    }
#pragma unroll 3
    for (int k = 0; k < NG; k++) {
        float4 a0 = *(const float4*)&sAT[k * 128 + e0];
        float4 a1 = *(const float4*)&sAT[k * 128 + e0 + 4];
        ulonglong2 bq = *(const ulonglong2*)&sW1[k * 128 + f0];
        float av[8] = {a0.x,a0.y,a0.z,a0.w,a1.x,a1.y,a1.z,a1.w};
        FFMA2_BLOCK84(acc2, av, bq);
    }

    // ssp -> sT
#pragma unroll
    for (int i = 0; i < 8; i++) {
        float2 v0 = unpack2(acc2[i][0]), v1 = unpack2(acc2[i][1]);
        float* tp = &sT[(e0 + i) * 132 + f0];
        tp[0] = ssp_f(v0.x); tp[1] = ssp_f(v0.y);
        tp[2] = ssp_f(v1.x); tp[3] = ssp_f(v1.y);
    }
    __syncthreads();

    // ---- GEMM2: K = 128 ----
    {
        ulonglong2 bb = *(const ulonglong2*)(B2 + f0);
#pragma unroll
        for (int i = 0; i < 8; i++) { acc2[i][0] = bb.x; acc2[i][1] = bb.y; }
    }
#pragma unroll 1
    for (int k4 = 0; k4 < 128; k4 += 4) {
        float4 av4[8];
#pragma unroll
        for (int i = 0; i < 8; i++)
            av4[i] = *(const float4*)&sT[(e0 + i) * 132 + k4];
#pragma unroll
        for (int kk = 0; kk < 4; kk++) {
            ulonglong2 bq = *(const ulonglong2*)&sW2[(k4 + kk) * 128 + f0];
            float av[8];
#pragma unroll
            for (int i = 0; i < 8; i++) av[i] = ((const float*)&av4[i])[kk];
            FFMA2_BLOCK84(acc2, av, bq);
        }
    }

    // epilogue: *C, gather xh[col], scatter-add to agg[row]
#pragma unroll
    for (int i = 0; i < 8; i++) {
        int le = e0 + i;
        unsigned long long cd = dup2(sC[le]);
        int cl = sCol[le], rw = sRow[le];
        const float* xr = g_xh + (size_t)cl * HID + f0;
        ulonglong2 xq = *(const ulonglong2*)xr;
        unsigned long long p0 = mul2(mul2(acc2[i][0], cd), xq.x);
        unsigned long long p1 = mul2(mul2(acc2[i][1], cd), xq.y);
        float2 u0 = unpack2(p0), u1 = unpack2(p1);
        red_add_v4(g_agg + (size_t)rw * HID + f0,
                   make_float4(u0.x, u0.y, u1.x, u1.y));
    }
}

// ---------------- fused dual node GEMM (512 thr, 8x4 tile) ------------------
__global__ __launch_bounds__(512, 1)
void k_dual(const float* __restrict__ X,
            const float* __restrict__ W1, const float* __restrict__ B1,
            const float* __restrict__ W2, const float* __restrict__ B2,
            float* __restrict__ dst, int addMode) {
    extern __shared__ float sm[];
    float* sX  = sm;                  // 128*132 (re-used as T after GEMM1)
    float* sW1 = sm + 128 * 132;      // 128*128
    float* sW2 = sW1 + 128 * 128;     // 128*128
    int tid = threadIdx.x;
    int rBase = blockIdx.x * 128;

    for (int i = tid; i < 128 * 32; i += 512) {
        int r = i >> 5, c = i & 31;
        ((float4*)(sX + r * 132))[c] =
            ((const float4*)(X + (size_t)(rBase + r) * HID))[c];
    }
    for (int i = tid; i < 128 * 32; i += 512)
        ((float4*)sW1)[i] = ((const float4*)W1)[i];
    for (int i = tid; i < 128 * 32; i += 512)
        ((float4*)sW2)[i] = ((const float4*)W2)[i];
    __syncthreads();

    int tr = tid >> 5, tc = tid & 31, r0 = tr * 8, f0 = tc * 4;
    unsigned long long acc2[8][2];

    // ---- GEMM1 ----
    {
        ulonglong2 bb = *(const ulonglong2*)(B1 + f0);
#pragma unroll
        for (int i = 0; i < 8; i++) { acc2[i][0] = bb.x; acc2[i][1] = bb.y; }
    }
#pragma unroll 1
    for (int k4 = 0; k4 < 128; k4 += 4) {
        float4 av4[8];
#pragma unroll
        for (int i = 0; i < 8; i++)
            av4[i] = *(const float4*)&sX[(r0 + i) * 132 + k4];
#pragma unroll
        for (int kk = 0; kk < 4; kk++) {
            ulonglong2 bq = *(const ulonglong2*)&sW1[(k4 + kk) * 128 + f0];
            float av[8];
#pragma unroll
            for (int i = 0; i < 8; i++) av[i] = ((const float*)&av4[i])[kk];
            FFMA2_BLOCK84(acc2, av, bq);
        }
    }
    __syncthreads();   // everyone done reading sX before it becomes T
#pragma unroll
    for (int i = 0; i < 8; i++) {
        float2 v0 = unpack2(acc2[i][0]), v1 = unpack2(acc2[i][1]);
        float* tp = &sX[(r0 + i) * 132 + f0];
        tp[0] = ssp_f(v0.x); tp[1] = ssp_f(v0.y);
        tp[2] = ssp_f(v1.x); tp[3] = ssp_f(v1.y);
    }
    __syncthreads();

    // ---- GEMM2 ----
    {
        ulonglong2 bb = *(const ulonglong2*)(B2 + f0);
#pragma unroll
        for (int i = 0; i < 8; i++) { acc2[i][0] = bb.x; acc2[i][1] = bb.y; }
    }
#pragma unroll 1
    for (int k4 = 0; k4 < 128; k4 += 4) {
        float4 av4[8];
#pragma unroll
        for (int i = 0; i < 8; i++)
            av4[i] = *(const float4*)&sX[(r0 + i) * 132 + k4];
#pragma unroll
        for (int kk = 0; kk < 4; kk++) {
            ulonglong2 bq = *(const ulonglong2*)&sW2[(k4 + kk) * 128 + f0];
            float av[8];
#pragma unroll
            for (int i = 0; i < 8; i++) av[i] = ((const float*)&av4[i])[kk];
            FFMA2_BLOCK84(acc2, av, bq);
        }
    }
#pragma unroll
    for (int i = 0; i < 8; i++) {
        float2 u0 = unpack2(acc2[i][0]), u1 = unpack2(acc2[i][1]);
        float* dp = dst + (size_t)(rBase + r0 + i) * HID + f0;
        if (addMode) {
            float4 d0 = *(float4*)dp;
            d0.x += u0.x; d0.y += u0.y; d0.z += u1.x; d0.w += u1.y;
            *(float4*)dp = d0;
        } else {
            *(float4*)dp = make_float4(u0.x, u0.y, u1.x, u1.y);
        }
    }
}

// ---------------- pooling --------------------------------------------------
__global__ void k_zero_out(float* __restrict__ out) {
    int idx = blockIdx.x * 256 + threadIdx.x;
    if (idx < GG * HID) out[idx] = 0.f;
    if (idx < GG) g_cnt[idx] = 0.f;
}

__global__ void k_pool(const int* __restrict__ batch, float* __restrict__ out) {
    int idx = blockIdx.x * 256 + threadIdx.x;      // NN*32 threads
    int n = idx >> 5, q = idx & 31;
    float4 v = ((const float4*)(g_h2 + (size_t)n * HID))[q];
    int b = batch[n];
    red_add_v4(out + (size_t)b * HID + q * 4, v);
    if (q == 0) atomicAdd(&g_cnt[b], 1.f);
}

__global__ void k_div(float* __restrict__ out) {
    int idx = blockIdx.x * 256 + threadIdx.x;
    if (idx < GG * HID) {
        int g = idx >> 7;
        out[idx] = out[idx] / fmaxf(g_cnt[g], 1.f);
    }
}

// ---------------- host side ------------------------------------------------
extern "C" void kernel_launch(void* const* d_in, const int* in_sizes, int n_in,
                              void* d_out, int out_size) {
    const int*   z       = (const int*)  d_in[0];
    const float* pos     = (const float*)d_in[1];
    const int*   batch   = (const int*)  d_in[2];
    const int*   ei      = (const int*)  d_in[3];
    const float* emb     = (const float*)d_in[4];
    const float* mlp1_w  = (const float*)d_in[5];
    const float* mlp1_b  = (const float*)d_in[6];
    const float* mlp2_w  = (const float*)d_in[7];
    const float* mlp2_b  = (const float*)d_in[8];
    const float* cl1_w   = (const float*)d_in[9];
    const float* cl2_w   = (const float*)d_in[10];
    const float* cl2_b   = (const float*)d_in[11];
    const float* lin_w   = (const float*)d_in[12];
    const float* lin_b   = (const float*)d_in[13];
    const float* out1_w  = (const float*)d_in[14];
    const float* out1_b  = (const float*)d_in[15];
    const float* out2_w  = (const float*)d_in[16];
    const float* out2_b  = (const float*)d_in[17];
    float* out = (float*)d_out;

    float *p_agg, *p_h, *p_h2;
    cudaGetSymbolAddress((void**)&p_agg, g_agg);
    cudaGetSymbolAddress((void**)&p_h,   g_h);
    cudaGetSymbolAddress((void**)&p_h2,  g_h2);

    const int smEdge = (NG*128*2 + 128*128 + 128*132 + 128) * 4 + 256 * 4;
    const int smDual = (128*132 + 2*128*128) * 4;
    const int smG    = (128*132 + 128*128) * 4;
    cudaFuncSetAttribute(k_edge,    cudaFuncAttributeMaxDynamicSharedMemorySize, smEdge);
    cudaFuncSetAttribute(k_dual,    cudaFuncAttributeMaxDynamicSharedMemorySize, smDual);
    cudaFuncSetAttribute(k_gemm_xh, cudaFuncAttributeMaxDynamicSharedMemorySize, smG);

    k_init_h  <<<NN * 32 / 256, 256>>>(z, emb);
    k_edge_pre<<<EE / 128, 128>>>(pos, ei);

    for (int l = 0; l < NL; l++) {
        k_zero_agg<<<NN * HID / 4 / 256, 256>>>();
        k_gemm_xh<<<NN / 128, 512, smG>>>(cl1_w + (size_t)l * HID * HID);
        k_edge<<<EE / 128, 512, smEdge>>>(ei,
            mlp1_w + (size_t)l * NG * HID, mlp1_b + (size_t)l * HID,
            mlp2_w + (size_t)l * HID * HID, mlp2_b + (size_t)l * HID);
        k_dual<<<NN / 128, 512, smDual>>>(p_agg,
            cl2_w + (size_t)l * HID * HID, cl2_b + (size_t)l * HID,
            lin_w + (size_t)l * HID * HID, lin_b + (size_t)l * HID,
            p_h, 1);
    }

    // final output MLP then scatter-mean pooling
    k_dual<<<NN / 128, 512, smDual>>>(p_h, out1_w, out1_b, out2_w, out2_b, p_h2, 0);
    k_zero_out<<<(GG * HID + 255) / 256, 256>>>(out);
    k_pool<<<NN * 32 / 256, 256>>>(batch, out);
    k_div<<<(GG * HID + 255) / 256, 256>>>(out);
}

// round 11
// speedup vs baseline: 1.2804x; 1.0129x over previous
#include <cuda_runtime.h>

#define NN   16384
#define EE   524288
#define GG   64
#define HID  128
#define NG   51
#define NL   6

// ---------------- scratch (device globals; no allocation allowed) ----------
__device__ float g_h   [(size_t)NN * HID];   // node features
__device__ float g_h2  [(size_t)NN * HID];   // final MLP output
__device__ float g_xh  [(size_t)NN * HID];   // h @ cl1_w
__device__ float g_agg [(size_t)NN * HID];   // segment-sum accumulator
__device__ float g_attrT[(size_t)NG * EE];   // gaussian smearing, [k][e] layout
__device__ float g_C   [EE];                 // cosine cutoff
__device__ float g_cnt [GG];                 // per-graph node counts

// ---------------- helpers --------------------------------------------------
__device__ __forceinline__ float ssp_f(float x) {
    float sp = (x > 15.f) ? x : __logf(1.f + __expf(x));
    return sp - 0.69314718055994531f;
}

__device__ __forceinline__ void red_add_v4(float* addr, float4 v) {
    asm volatile("red.global.add.v4.f32 [%0], {%1,%2,%3,%4};"
                 :: "l"(addr), "f"(v.x), "f"(v.y), "f"(v.z), "f"(v.w)
                 : "memory");
}

// ---- packed f32x2 primitives (FFMA2: ptxas only emits via fma.rn.f32x2) ----
__device__ __forceinline__ unsigned long long dup2(float a) {
    unsigned long long r;
    asm("mov.b64 %0, {%1, %1};" : "=l"(r) : "f"(a));
    return r;
}
__device__ __forceinline__ void ffma2(unsigned long long& acc,
                                      unsigned long long a, unsigned long long b) {
    asm("fma.rn.f32x2 %0, %1, %2, %0;" : "+l"(acc) : "l"(a), "l"(b));
}
__device__ __forceinline__ unsigned long long mul2(unsigned long long a,
                                                   unsigned long long b) {
    unsigned long long r;
    asm("mul.rn.f32x2 %0, %1, %2;" : "=l"(r) : "l"(a), "l"(b));
    return r;
}
__device__ __forceinline__ float2 unpack2(unsigned long long v) {
    float2 r;
    asm("mov.b64 {%0, %1}, %2;" : "=f"(r.x), "=f"(r.y) : "l"(v));
    return r;
}

// inner block for 4x4 thread tile: acc2[4][2] += av[4] (x) B pair-of-pairs
#define FFMA2_BLOCK44(acc2, av, bq)                                       \
    _Pragma("unroll")                                                     \
    for (int _i = 0; _i < 4; _i++) {                                      \
        unsigned long long _ad = dup2((av)[_i]);                          \
        ffma2((acc2)[_i][0], _ad, (bq).x);                                \
        ffma2((acc2)[_i][1], _ad, (bq).y);                                \
    }

// ---------------- setup kernels --------------------------------------------
__global__ void k_init_h(const int* __restrict__ z, const float* __restrict__ emb) {
    int idx = blockIdx.x * 256 + threadIdx.x;      // NN*32 threads
    int n = idx >> 5, q = idx & 31;
    ((float4*)g_h)[idx] = ((const float4*)(emb + (size_t)z[n] * HID))[q];
}

__global__ void k_edge_pre(const float* __restrict__ pos, const int* __restrict__ ei) {
    __shared__ float sA[NG * 128];
    int t = threadIdx.x;
    int eBase = blockIdx.x * 128;
    int e = eBase + t;
    int r = ei[e], c = ei[EE + e];
    float dx = pos[r*3+0] - pos[c*3+0];
    float dy = pos[r*3+1] - pos[c*3+1];
    float dz = pos[r*3+2] - pos[c*3+2];
    float d = sqrtf(dx*dx + dy*dy + dz*dz);
    g_C[e] = 0.5f * (__cosf(d * 0.31415926535897931f) + 1.f);
#pragma unroll
    for (int k = 0; k < NG; k++) {
        float u = d - 0.2f * (float)k;
        sA[k * 128 + t] = __expf(-12.5f * u * u);
    }
    __syncthreads();
    for (int i = t; i < NG * 128; i += 128) {
        int k = i >> 7, q = i & 127;
        g_attrT[(size_t)k * EE + eBase + q] = sA[i];
    }
}

__global__ void k_zero_agg() {
    int idx = blockIdx.x * 256 + threadIdx.x;      // NN*HID/4 threads
    ((float4*)g_agg)[idx] = make_float4(0.f, 0.f, 0.f, 0.f);
}

// ---------------- node GEMM: xh = h @ W (1024 thr, 4x4 tile) ----------------
__global__ __launch_bounds__(1024, 1)
void k_gemm_xh(const float* __restrict__ W) {
    extern __shared__ float sm[];
    float* sX = sm;                  // 128*132
    float* sW = sm + 128 * 132;      // 128*128
    int tid = threadIdx.x;
    int rBase = blockIdx.x * 128;

    for (int i = tid; i < 128 * 32; i += 1024) {
        int r = i >> 5, c = i & 31;
        ((float4*)(sX + r * 132))[c] =
            ((const float4*)(g_h + (size_t)(rBase + r) * HID))[c];
    }
    for (int i = tid; i < 128 * 32; i += 1024)
        ((float4*)sW)[i] = ((const float4*)W)[i];
    __syncthreads();

    int tr = tid >> 5, tc = tid & 31, r0 = tr * 4, f0 = tc * 4;
    unsigned long long acc2[4][2];
#pragma unroll
    for (int i = 0; i < 4; i++) { acc2[i][0] = 0ull; acc2[i][1] = 0ull; }

#pragma unroll 1
    for (int k4 = 0; k4 < 128; k4 += 4) {
        float4 av4[4];
#pragma unroll
        for (int i = 0; i < 4; i++)
            av4[i] = *(const float4*)&sX[(r0 + i) * 132 + k4];
#pragma unroll
        for (int kk = 0; kk < 4; kk++) {
            ulonglong2 bq = *(const ulonglong2*)&sW[(k4 + kk) * 128 + f0];
            float av[4];
#pragma unroll
            for (int i = 0; i < 4; i++) av[i] = ((const float*)&av4[i])[kk];
            FFMA2_BLOCK44(acc2, av, bq);
        }
    }
#pragma unroll
    for (int i = 0; i < 4; i++) {
        float2 u0 = unpack2(acc2[i][0]), u1 = unpack2(acc2[i][1]);
        *(float4*)(g_xh + (size_t)(rBase + r0 + i) * HID + f0) =
            make_float4(u0.x, u0.y, u1.x, u1.y);
    }
}

// ---------------- fused edge kernel (1024 thr, 4x4 tile) --------------------
__global__ __launch_bounds__(1024, 1)
void k_edge(const int* __restrict__ ei,
            const float* __restrict__ W1, const float* __restrict__ B1,
            const float* __restrict__ W2, const float* __restrict__ B2) {
    extern __shared__ float sm[];
    float* sAT = sm;                       // NG*128
    float* sW1 = sAT + NG * 128;           // NG*128
    float* sW2 = sW1 + NG * 128;           // 128*128
    float* sT  = sW2 + 128 * 128;          // 128*132
    float* sC  = sT  + 128 * 132;          // 128
    int*   sRow = (int*)(sC + 128);        // 128
    int*   sCol = sRow + 128;              // 128

    int tid = threadIdx.x;
    int eBase = blockIdx.x * 128;

    for (int i = tid; i < NG * 32; i += 1024) {
        int k = i >> 5, q = i & 31;
        ((float4*)sAT)[i] = ((const float4*)(g_attrT + (size_t)k * EE + eBase))[q];
    }
    for (int i = tid; i < NG * 32; i += 1024)
        ((float4*)sW1)[i] = ((const float4*)W1)[i];
    for (int i = tid; i < 128 * 32; i += 1024)
        ((float4*)sW2)[i] = ((const float4*)W2)[i];
    if (tid < 128) {
        sC[tid]   = g_C[eBase + tid];
        sRow[tid] = ei[eBase + tid];
        sCol[tid] = ei[EE + eBase + tid];
    }
    __syncthreads();

    int tr = tid >> 5, tc = tid & 31, e0 = tr * 4, f0 = tc * 4;
    unsigned long long acc2[4][2];

    // ---- GEMM1: K = 51 ----
    {
        ulonglong2 bb = *(const ulonglong2*)(B1 + f0);
#pragma unroll
        for (int i = 0; i < 4; i++) { acc2[i][0] = bb.x; acc2[i][1] = bb.y; }
    }
#pragma unroll 3
    for (int k = 0; k < NG; k++) {
        float4 a0 = *(const float4*)&sAT[k * 128 + e0];
        ulonglong2 bq = *(const ulonglong2*)&sW1[k * 128 + f0];
        float av[4] = {a0.x, a0.y, a0.z, a0.w};
        FFMA2_BLOCK44(acc2, av, bq);
    }

    // ssp -> sT (float4 stores; (e)*132+f0 is 16B aligned)
#pragma unroll
    for (int i = 0; i < 4; i++) {
        float2 v0 = unpack2(acc2[i][0]), v1 = unpack2(acc2[i][1]);
        *(float4*)&sT[(e0 + i) * 132 + f0] =
            make_float4(ssp_f(v0.x), ssp_f(v0.y), ssp_f(v1.x), ssp_f(v1.y));
    }
    __syncthreads();

    // ---- GEMM2: K = 128 ----
    {
        ulonglong2 bb = *(const ulonglong2*)(B2 + f0);
#pragma unroll
        for (int i = 0; i < 4; i++) { acc2[i][0] = bb.x; acc2[i][1] = bb.y; }
    }
#pragma unroll 1
    for (int k4 = 0; k4 < 128; k4 += 4) {
        float4 av4[4];
#pragma unroll
        for (int i = 0; i < 4; i++)
            av4[i] = *(const float4*)&sT[(e0 + i) * 132 + k4];
#pragma unroll
        for (int kk = 0; kk < 4; kk++) {
            ulonglong2 bq = *(const ulonglong2*)&sW2[(k4 + kk) * 128 + f0];
            float av[4];
#pragma unroll
            for (int i = 0; i < 4; i++) av[i] = ((const float*)&av4[i])[kk];
            FFMA2_BLOCK44(acc2, av, bq);
        }
    }

    // epilogue: *C, gather xh[col], scatter-add to agg[row]
#pragma unroll
    for (int i = 0; i < 4; i++) {
        int le = e0 + i;
        unsigned long long cd = dup2(sC[le]);
        int cl = sCol[le], rw = sRow[le];
        const float* xr = g_xh + (size_t)cl * HID + f0;
        ulonglong2 xq = *(const ulonglong2*)xr;
        unsigned long long p0 = mul2(mul2(acc2[i][0], cd), xq.x);
        unsigned long long p1 = mul2(mul2(acc2[i][1], cd), xq.y);
        float2 u0 = unpack2(p0), u1 = unpack2(p1);
        red_add_v4(g_agg + (size_t)rw * HID + f0,
                   make_float4(u0.x, u0.y, u1.x, u1.y));
    }
}

// ---------------- fused dual node GEMM (1024 thr, 4x4 tile) -----------------
__global__ __launch_bounds__(1024, 1)
void k_dual(const float* __restrict__ X,
            const float* __restrict__ W1, const float* __restrict__ B1,
            const float* __restrict__ W2, const float* __restrict__ B2,
            float* __restrict__ dst, int addMode) {
    extern __shared__ float sm[];
    float* sX  = sm;                  // 128*132 (re-used as T after GEMM1)
    float* sW1 = sm + 128 * 132;      // 128*128
    float* sW2 = sW1 + 128 * 128;     // 128*128
    int tid = threadIdx.x;
    int rBase = blockIdx.x * 128;

    for (int i = tid; i < 128 * 32; i += 1024) {
        int r = i >> 5, c = i & 31;
        ((float4*)(sX + r * 132))[c] =
            ((const float4*)(X + (size_t)(rBase + r) * HID))[c];
    }
    for (int i = tid; i < 128 * 32; i += 1024)
        ((float4*)sW1)[i] = ((const float4*)W1)[i];
    for (int i = tid; i < 128 * 32; i += 1024)
        ((float4*)sW2)[i] = ((const float4*)W2)[i];
    __syncthreads();

    int tr = tid >> 5, tc = tid & 31, r0 = tr * 4, f0 = tc * 4;
    unsigned long long acc2[4][2];

    // ---- GEMM1 ----
    {
        ulonglong2 bb = *(const ulonglong2*)(B1 + f0);
#pragma unroll
        for (int i = 0; i < 4; i++) { acc2[i][0] = bb.x; acc2[i][1] = bb.y; }
    }
#pragma unroll 1
    for (int k4 = 0; k4 < 128; k4 += 4) {
        float4 av4[4];
#pragma unroll
        for (int i = 0; i < 4; i++)
            av4[i] = *(const float4*)&sX[(r0 + i) * 132 + k4];
#pragma unroll
        for (int kk = 0; kk < 4; kk++) {
            ulonglong2 bq = *(const ulonglong2*)&sW1[(k4 + kk) * 128 + f0];
            float av[4];
#pragma unroll
            for (int i = 0; i < 4; i++) av[i] = ((const float*)&av4[i])[kk];
            FFMA2_BLOCK44(acc2, av, bq);
        }
    }
    __syncthreads();   // everyone done reading sX before it becomes T
#pragma unroll
    for (int i = 0; i < 4; i++) {
        float2 v0 = unpack2(acc2[i][0]), v1 = unpack2(acc2[i][1]);
        *(float4*)&sX[(r0 + i) * 132 + f0] =
            make_float4(ssp_f(v0.x), ssp_f(v0.y), ssp_f(v1.x), ssp_f(v1.y));
    }
    __syncthreads();

    // ---- GEMM2 ----
    {
        ulonglong2 bb = *(const ulonglong2*)(B2 + f0);
#pragma unroll
        for (int i = 0; i < 4; i++) { acc2[i][0] = bb.x; acc2[i][1] = bb.y; }
    }
#pragma unroll 1
    for (int k4 = 0; k4 < 128; k4 += 4) {
        float4 av4[4];
#pragma unroll
        for (int i = 0; i < 4; i++)
            av4[i] = *(const float4*)&sX[(r0 + i) * 132 + k4];
#pragma unroll
        for (int kk = 0; kk < 4; kk++) {
            ulonglong2 bq = *(const ulonglong2*)&sW2[(k4 + kk) * 128 + f0];
            float av[4];
#pragma unroll
            for (int i = 0; i < 4; i++) av[i] = ((const float*)&av4[i])[kk];
            FFMA2_BLOCK44(acc2, av, bq);
        }
    }
#pragma unroll
    for (int i = 0; i < 4; i++) {
        float2 u0 = unpack2(acc2[i][0]), u1 = unpack2(acc2[i][1]);
        float* dp = dst + (size_t)(rBase + r0 + i) * HID + f0;
        if (addMode) {
            float4 d0 = *(float4*)dp;
            d0.x += u0.x; d0.y += u0.y; d0.z += u1.x; d0.w += u1.y;
            *(float4*)dp = d0;
        } else {
            *(float4*)dp = make_float4(u0.x, u0.y, u1.x, u1.y);
        }
    }
}

// ---------------- pooling --------------------------------------------------
__global__ void k_zero_out(float* __restrict__ out) {
    int idx = blockIdx.x * 256 + threadIdx.x;
    if (idx < GG * HID) out[idx] = 0.f;
    if (idx < GG) g_cnt[idx] = 0.f;
}

__global__ void k_pool(const int* __restrict__ batch, float* __restrict__ out) {
    int idx = blockIdx.x * 256 + threadIdx.x;      // NN*32 threads
    int n = idx >> 5, q = idx & 31;
    float4 v = ((const float4*)(g_h2 + (size_t)n * HID))[q];
    int b = batch[n];
    red_add_v4(out + (size_t)b * HID + q * 4, v);
    if (q == 0) atomicAdd(&g_cnt[b], 1.f);
}

__global__ void k_div(float* __restrict__ out) {
    int idx = blockIdx.x * 256 + threadIdx.x;
    if (idx < GG * HID) {
        int g = idx >> 7;
        out[idx] = out[idx] / fmaxf(g_cnt[g], 1.f);
    }
}

// ---------------- host side ------------------------------------------------
extern "C" void kernel_launch(void* const* d_in, const int* in_sizes, int n_in,
                              void* d_out, int out_size) {
    const int*   z       = (const int*)  d_in[0];
    const float* pos     = (const float*)d_in[1];
    const int*   batch   = (const int*)  d_in[2];
    const int*   ei      = (const int*)  d_in[3];
    const float* emb     = (const float*)d_in[4];
    const float* mlp1_w  = (const float*)d_in[5];
    const float* mlp1_b  = (const float*)d_in[6];
    const float* mlp2_w  = (const float*)d_in[7];
    const float* mlp2_b  = (const float*)d_in[8];
    const float* cl1_w   = (const float*)d_in[9];
    const float* cl2_w   = (const float*)d_in[10];
    const float* cl2_b   = (const float*)d_in[11];
    const float* lin_w   = (const float*)d_in[12];
    const float* lin_b   = (const float*)d_in[13];
    const float* out1_w  = (const float*)d_in[14];
    const float* out1_b  = (const float*)d_in[15];
    const float* out2_w  = (const float*)d_in[16];
    const float* out2_b  = (const float*)d_in[17];
    float* out = (float*)d_out;

    float *p_agg, *p_h, *p_h2;
    cudaGetSymbolAddress((void**)&p_agg, g_agg);
    cudaGetSymbolAddress((void**)&p_h,   g_h);
    cudaGetSymbolAddress((void**)&p_h2,  g_h2);

    const int smEdge = (NG*128*2 + 128*128 + 128*132 + 128) * 4 + 256 * 4;
    const int smDual = (128*132 + 2*128*128) * 4;
    const int smG    = (128*132 + 128*128) * 4;
    cudaFuncSetAttribute(k_edge,    cudaFuncAttributeMaxDynamicSharedMemorySize, smEdge);
    cudaFuncSetAttribute(k_dual,    cudaFuncAttributeMaxDynamicSharedMemorySize, smDual);
    cudaFuncSetAttribute(k_gemm_xh, cudaFuncAttributeMaxDynamicSharedMemorySize, smG);

    k_init_h  <<<NN * 32 / 256, 256>>>(z, emb);
    k_edge_pre<<<EE / 128, 128>>>(pos, ei);

    for (int l = 0; l < NL; l++) {
        k_zero_agg<<<NN * HID / 4 / 256, 256>>>();
        k_gemm_xh<<<NN / 128, 1024, smG>>>(cl1_w + (size_t)l * HID * HID);
        k_edge<<<EE / 128, 1024, smEdge>>>(ei,
            mlp1_w + (size_t)l * NG * HID, mlp1_b + (size_t)l * HID,
            mlp2_w + (size_t)l * HID * HID, mlp2_b + (size_t)l * HID);
        k_dual<<<NN / 128, 1024, smDual>>>(p_agg,
            cl2_w + (size_t)l * HID * HID, cl2_b + (size_t)l * HID,
            lin_w + (size_t)l * HID * HID, lin_b + (size_t)l * HID,
            p_h, 1);
    }

    // final output MLP then scatter-mean pooling
    k_dual<<<NN / 128, 1024, smDual>>>(p_h, out1_w, out1_b, out2_w, out2_b, p_h2, 0);
    k_zero_out<<<(GG * HID + 255) / 256, 256>>>(out);
    k_pool<<<NN * 32 / 256, 256>>>(batch, out);
    k_div<<<(GG * HID + 255) / 256, 256>>>(out);
}